// round 12
// baseline (speedup 1.0000x reference)
#include <cuda_runtime.h>
#include <cuda_fp16.h>
#include <math.h>
#include <stdint.h>

// Problem shape (fixed)
#define NTOK 2048      // B*T
#define HDIM 1024      // H
#define FDIM 4096      // F
#define NEXP 8         // E
#define TOPK 2
#define NOISE_SCALE 0.01f

// GEMM tiling
#define BM 128
#define BN 64
#define BK 64
#define AS_STR 72              // BK + 8 pad (fp16 elems); row stride 144 B (16-aligned)
#define ATILE (BM * AS_STR)    // 9216 elems
#define BTILE (BN * AS_STR)    // 4608 elems
#define NSTG 3                 // pipeline stages (prefetch distance 2)

// ---------------- device scratch (allocation-free) ---------------------------
__device__ int   g_sel[NTOK * TOPK];
__device__ float g_wt [NTOK * TOPK];
__device__ int   g_cnt[NEXP];
__device__ int   g_list[NEXP * NTOK];
__device__ float g_lw  [NEXP * NTOK];

// fp16 weights transposed to [E][N][K]; fp16 x and activations
__device__ __align__(16) __half g_w1t[(size_t)NEXP * FDIM * HDIM];
__device__ __align__(16) __half g_w3t[(size_t)NEXP * FDIM * HDIM];
__device__ __align__(16) __half g_w2t[(size_t)NEXP * HDIM * FDIM];
__device__ __align__(16) __half g_x16[(size_t)NTOK * HDIM];
__device__ __align__(16) __half g_act[(size_t)NEXP * NTOK * FDIM];

__device__ __forceinline__ float siluf(float v) { return v / (1.0f + expf(-v)); }

#define MMA_F16(d, a0,a1,a2,a3, b0,b1)                                           \
    asm volatile("mma.sync.aligned.m16n8k16.row.col.f32.f16.f16.f32 "            \
                 "{%0,%1,%2,%3},{%4,%5,%6,%7},{%8,%9},{%0,%1,%2,%3};\n"          \
                 : "+f"(d[0]), "+f"(d[1]), "+f"(d[2]), "+f"(d[3])                \
                 : "r"(a0), "r"(a1), "r"(a2), "r"(a3), "r"(b0), "r"(b1))

#define LDSM4(r0,r1,r2,r3, addr)                                                 \
    asm volatile("ldmatrix.sync.aligned.m8n8.x4.shared.b16 {%0,%1,%2,%3}, [%4];" \
                 : "=r"(r0), "=r"(r1), "=r"(r2), "=r"(r3) : "r"(addr))

__device__ __forceinline__ void cpa16(unsigned dst, const void* src) {
    asm volatile("cp.async.ca.shared.global [%0], [%1], 16;\n" :: "r"(dst), "l"(src));
}
#define CP_COMMIT() asm volatile("cp.async.commit_group;\n")
#define CP_WAIT0()  asm volatile("cp.async.wait_group 0;\n")
#define CP_WAIT1()  asm volatile("cp.async.wait_group 1;\n")

// ---------------- conversion: x fp32 -> fp16 ---------------------------------
__global__ void convert_x_kernel(const float* __restrict__ x) {
    int i = blockIdx.x * blockDim.x + threadIdx.x;   // one float4 per thread
    float4 v = reinterpret_cast<const float4*>(x)[i];
    __half2 h0 = __floats2half2_rn(v.x, v.y);
    __half2 h1 = __floats2half2_rn(v.z, v.w);
    uint2 o;
    o.x = *reinterpret_cast<unsigned*>(&h0);
    o.y = *reinterpret_cast<unsigned*>(&h1);
    reinterpret_cast<uint2*>(g_x16)[i] = o;
}

// ---------------- fused transpose+convert for W1, W3, W2 ---------------------
// W[e][K][N] f32 -> Wt[e][N][K] fp16; tile 64(k) x 32(n); 128B coalesced stores.
// z = mat*NEXP + e; grid.x = (K/64)*(N/32) = 2048 for all three shapes.
__global__ void transpose_convert_all(const float* __restrict__ W1,
                                      const float* __restrict__ W3,
                                      const float* __restrict__ W2) {
    __shared__ float tile[64][33];
    int z = blockIdx.z;
    int mat = z >> 3;          // 0:W1, 1:W3, 2:W2
    int e   = z & 7;
    const float* W;
    __half* Wt;
    int K, N;
    if (mat == 0)      { W = W1; Wt = g_w1t; K = HDIM; N = FDIM; }
    else if (mat == 1) { W = W3; Wt = g_w3t; K = HDIM; N = FDIM; }
    else               { W = W2; Wt = g_w2t; K = FDIM; N = HDIM; }

    int ntn = N >> 5;
    int n0 = (blockIdx.x % ntn) << 5;
    int k0 = (blockIdx.x / ntn) << 6;

    const float* We = W + (size_t)e * K * N;
    int tx = threadIdx.x, ty = threadIdx.y;   // 32 x 8
#pragma unroll
    for (int j = 0; j < 64; j += 8)
        tile[ty + j][tx] = We[(size_t)(k0 + ty + j) * N + n0 + tx];
    __syncthreads();
    size_t base = (size_t)e * K * N;
#pragma unroll
    for (int j = 0; j < 32; j += 8) {
        int n = ty + j;
        __half2 hv = __floats2half2_rn(tile[2 * tx][n], tile[2 * tx + 1][n]);
        *(__half2*)&Wt[base + (size_t)(n0 + n) * K + k0 + 2 * tx] = hv;
    }
}

// ---------------- router -----------------------------------------------------
__global__ void router_kernel(const float* __restrict__ x,
                              const float* __restrict__ noise,
                              const float* __restrict__ Wg,
                              const float* __restrict__ bg,
                              float* out_logits, float* out_sel) {
    int n = blockIdx.x;
    int tid = threadIdx.x;          // 128
    const float* xr = x + (size_t)n * HDIM;

    float acc[NEXP];
#pragma unroll
    for (int e = 0; e < NEXP; e++) acc[e] = 0.0f;
    for (int h = tid; h < HDIM; h += 128) {
        float xv = xr[h];
        const float* wr = Wg + (size_t)h * NEXP;
#pragma unroll
        for (int e = 0; e < NEXP; e++) acc[e] += xv * wr[e];
    }

    __shared__ float red[NEXP][128];
#pragma unroll
    for (int e = 0; e < NEXP; e++) red[e][tid] = acc[e];
    __syncthreads();
    for (int s = 64; s > 0; s >>= 1) {
        if (tid < s) {
#pragma unroll
            for (int e = 0; e < NEXP; e++) red[e][tid] += red[e][tid + s];
        }
        __syncthreads();
    }

    if (tid == 0) {
        float l[NEXP];
#pragma unroll
        for (int e = 0; e < NEXP; e++)
            l[e] = red[e][0] + bg[e] + NOISE_SCALE * noise[(size_t)n * NEXP + e];
        if (out_logits) {
#pragma unroll
            for (int e = 0; e < NEXP; e++)
                out_logits[(size_t)n * NEXP + e] = l[e];
        }
        int i0 = 0;
#pragma unroll
        for (int e = 1; e < NEXP; e++) if (l[e] > l[i0]) i0 = e;
        int i1 = (i0 == 0) ? 1 : 0;
#pragma unroll
        for (int e = 0; e < NEXP; e++) if (e != i0 && l[e] > l[i1]) i1 = e;

        float r = expf(l[i1] - l[i0]);
        float w0 = 1.0f / (1.0f + r);
        float w1 = r / (1.0f + r);
        g_sel[n * TOPK + 0] = i0;
        g_sel[n * TOPK + 1] = i1;
        g_wt [n * TOPK + 0] = w0;
        g_wt [n * TOPK + 1] = w1;
        if (out_sel) {
            out_sel[n * TOPK + 0] = (float)i0;
            out_sel[n * TOPK + 1] = (float)i1;
        }
    }
}

// ---------------- stable per-expert compaction (parallel) --------------------
// 1 block, 1024 threads = 32 warps: warp w -> expert (w&7), token-chunk (w>>3).
#define BL_CHUNK (NTOK / 4)            // 512 tokens per chunk
#define BL_ITER  (BL_CHUNK / 32)       // 16 ballots per warp
__global__ void build_lists_kernel() {
    __shared__ int      cnt_sh[NEXP][4];
    __shared__ unsigned mk_any[32][BL_ITER];
    __shared__ unsigned mk_m0 [32][BL_ITER];

    int tid = threadIdx.x, lane = tid & 31, w = tid >> 5;
    int e = w & 7, c = w >> 3;
    int tok0 = c * BL_CHUNK;

    int cc = 0;
#pragma unroll
    for (int i = 0; i < BL_ITER; i++) {
        int n = tok0 + i * 32 + lane;
        int s0 = g_sel[n * TOPK + 0];
        int s1 = g_sel[n * TOPK + 1];
        bool m0 = (s0 == e), m1 = (s1 == e);
        unsigned ma = __ballot_sync(0xffffffffu, m0 || m1);
        unsigned mz = __ballot_sync(0xffffffffu, m0);
        if (lane == 0) { mk_any[w][i] = ma; mk_m0[w][i] = mz; }
        cc += __popc(ma);
    }
    if (lane == 0) cnt_sh[e][c] = cc;
    __syncthreads();

    int base = 0;
#pragma unroll
    for (int k = 0; k < 4; k++) {
        if (k < c) base += cnt_sh[e][k];
    }
    if (c == 3 && lane == 0) g_cnt[e] = base + cnt_sh[e][3];

    int run = base;
#pragma unroll
    for (int i = 0; i < BL_ITER; i++) {
        unsigned ma = mk_any[w][i];
        unsigned mz = mk_m0[w][i];
        int n = tok0 + i * 32 + lane;
        if (ma & (1u << lane)) {
            int pos = run + __popc(ma & ((1u << lane) - 1u));
            g_list[e * NTOK + pos] = n;
            bool is0 = (mz >> lane) & 1u;
            g_lw[e * NTOK + pos] = g_wt[n * TOPK + (is0 ? 0 : 1)];
        }
        run += __popc(ma);
    }
}

// ---------------- GEMM1 (fp16 mma + ldmatrix): act = silu(X@W1+b1)*(X@W3+b3) -
// grid: (m=16, n=64, e=8), 256 threads, 3-stage cp.async, NOW 2 CTAs/SM
// dyn smem 110592 B/CTA; 2x110592 = 221184 B fits 228KB carveout
__global__ __launch_bounds__(256, 2)
void gemm1_kernel(const float* __restrict__ b1, const float* __restrict__ b3) {
    int e   = blockIdx.z;
    int cnt = g_cnt[e];
    int m0  = blockIdx.x * BM;
    if (m0 >= cnt) return;
    int n0  = blockIdx.y * BN;

    extern __shared__ __align__(16) __half smem[];
    const int STG = ATILE + 2 * BTILE;    // halves per stage
    __shared__ int toks[BM];

    int tid = threadIdx.x;
    if (tid < BM) {
        int r = m0 + tid;
        toks[tid] = (r < cnt) ? g_list[e * NTOK + r] : -1;
    }
    __syncthreads();

    // staging: A 1024 chunks (4/thread), B1 512 (2/thread), B3 512 (2/thread)
    int arow = tid >> 1, apart = (tid & 1) * 4;       // 4 consecutive 16B parts
    int tokA = toks[arow]; if (tokA < 0) tokA = 0;
    int brow = tid >> 2, bpart = (tid & 3) * 2;       // 2 consecutive parts

    const __half* pA  = g_x16 + (size_t)tokA * HDIM + apart * 8;
    const __half* pB1 = g_w1t + ((size_t)e * FDIM + n0 + brow) * HDIM + bpart * 8;
    const __half* pB3 = g_w3t + ((size_t)e * FDIM + n0 + brow) * HDIM + bpart * 8;

    unsigned uS0 = (unsigned)__cvta_generic_to_shared(smem);
    unsigned uA  = uS0 + (unsigned)(arow * AS_STR + apart * 8) * 2;
    unsigned uB1 = uS0 + (unsigned)(ATILE + brow * AS_STR + bpart * 8) * 2;
    unsigned uB3 = uS0 + (unsigned)(ATILE + BTILE + brow * AS_STR + bpart * 8) * 2;

#define G1_ISSUE(s, kof)                                                         \
    do {                                                                         \
        unsigned sb_ = (unsigned)(s) * STG * 2;                                  \
        cpa16(uA  + sb_,      pA  + (kof));                                      \
        cpa16(uA  + sb_ + 16, pA  + (kof) + 8);                                  \
        cpa16(uA  + sb_ + 32, pA  + (kof) + 16);                                 \
        cpa16(uA  + sb_ + 48, pA  + (kof) + 24);                                 \
        cpa16(uB1 + sb_,      pB1 + (kof));                                      \
        cpa16(uB1 + sb_ + 16, pB1 + (kof) + 8);                                  \
        cpa16(uB3 + sb_,      pB3 + (kof));                                      \
        cpa16(uB3 + sb_ + 16, pB3 + (kof) + 8);                                  \
        CP_COMMIT();                                                             \
    } while (0)

    // preload stages 0,1 (iterations 0,1)
    G1_ISSUE(0, 0);
    G1_ISSUE(1, BK);

    int lane = tid & 31, warp = tid >> 5;
    int wm = warp & 3, wn = warp >> 2;      // 4 x 2 warps -> 32x32 each
    int mb = wm * 32, nb = wn * 32;
    int r = lane >> 2, q = lane & 3;

    // ldmatrix lane addressing (4 groups of 8 lanes)
    int lr = lane & 7, lg = lane >> 3;
    int a_row  = mb + lr + 8 * (lg & 1);
    int a_koff = 8 * (lg >> 1);
    int b_col  = nb + lr + 8 * (lg >> 1);
    int b_koff = 8 * (lg & 1);

    unsigned aoff0 = (unsigned)(a_row * AS_STR + a_koff) * 2;            // A region rel
    unsigned aoff1 = aoff0 + (unsigned)(16 * AS_STR) * 2;
    unsigned boff0 = (unsigned)(b_col * AS_STR + b_koff) * 2;            // B region rel
    unsigned boff1 = boff0 + (unsigned)(16 * AS_STR) * 2;
    const unsigned uB1rel = (unsigned)ATILE * 2;
    const unsigned uB3rel = (unsigned)(ATILE + BTILE) * 2;

    float acc1[2][4][4], acc3[2][4][4];
#pragma unroll
    for (int i = 0; i < 2; i++)
#pragma unroll
        for (int j = 0; j < 4; j++)
#pragma unroll
            for (int c = 0; c < 4; c++) { acc1[i][j][c] = 0.f; acc3[i][j][c] = 0.f; }

    const int NIT = HDIM / BK;   // 16
    for (int it = 0; it < NIT; it++) {
        if (it < NIT - 1) CP_WAIT1(); else CP_WAIT0();
        __syncthreads();
        // prefetch it+2 into stage (it+2)%3: last READ at it-1; sync above orders it.
        if (it + 2 < NIT) G1_ISSUE((it + 2) % NSTG, (it + 2) * BK);

        int st = it % NSTG;
        unsigned uStage = uS0 + (unsigned)(st * STG) * 2;

#pragma unroll
        for (int ks = 0; ks < 4; ks++) {
            unsigned kb = (unsigned)ks * 32u;
            unsigned af0[4], af1[4];
            LDSM4(af0[0], af0[1], af0[2], af0[3], uStage + aoff0 + kb);
            LDSM4(af1[0], af1[1], af1[2], af1[3], uStage + aoff1 + kb);
#pragma unroll
            for (int jj = 0; jj < 2; jj++) {
                unsigned bo = (jj == 0) ? boff0 : boff1;
                unsigned p0, p1, p2, p3;
                LDSM4(p0, p1, p2, p3, uStage + uB1rel + bo + kb);
                MMA_F16(acc1[0][2*jj],   af0[0], af0[1], af0[2], af0[3], p0, p1);
                MMA_F16(acc1[1][2*jj],   af1[0], af1[1], af1[2], af1[3], p0, p1);
                MMA_F16(acc1[0][2*jj+1], af0[0], af0[1], af0[2], af0[3], p2, p3);
                MMA_F16(acc1[1][2*jj+1], af1[0], af1[1], af1[2], af1[3], p2, p3);
                unsigned t0, t1, t2, t3;
                LDSM4(t0, t1, t2, t3, uStage + uB3rel + bo + kb);
                MMA_F16(acc3[0][2*jj],   af0[0], af0[1], af0[2], af0[3], t0, t1);
                MMA_F16(acc3[1][2*jj],   af1[0], af1[1], af1[2], af1[3], t0, t1);
                MMA_F16(acc3[0][2*jj+1], af0[0], af0[1], af0[2], af0[3], t2, t3);
                MMA_F16(acc3[1][2*jj+1], af1[0], af1[1], af1[2], af1[3], t2, t3);
            }
        }
    }
#undef G1_ISSUE

    // epilogue: silu(h)*g -> fp16 act
#pragma unroll
    for (int j = 0; j < 4; j++) {
        int col = n0 + nb + 8 * j + q * 2;
        float2 bv1 = *(const float2*)(b1 + (size_t)e * FDIM + col);
        float2 bv3 = *(const float2*)(b3 + (size_t)e * FDIM + col);
#pragma unroll
        for (int i = 0; i < 2; i++) {
#pragma unroll
            for (int h = 0; h < 2; h++) {
                int rl = mb + 16 * i + r + 8 * h;
                int rr = m0 + rl;
                if (rr < cnt) {
                    float v0 = siluf(acc1[i][j][2*h+0] + bv1.x) * (acc3[i][j][2*h+0] + bv3.x);
                    float v1 = siluf(acc1[i][j][2*h+1] + bv1.y) * (acc3[i][j][2*h+1] + bv3.y);
                    __half2 hv = __floats2half2_rn(v0, v1);
                    *(__half2*)(g_act + ((size_t)e * NTOK + rr) * FDIM + col) = hv;
                }
            }
        }
    }
}

// ---------------- GEMM2 (fp16 mma + ldmatrix): out[tok] += w * (act@W2 + b2) -
// grid: (m=16, n=16, e=8), 256 threads, 3-stage pipeline, 2 CTAs/SM
__global__ __launch_bounds__(256, 2)
void gemm2_kernel(const float* __restrict__ b2, float* __restrict__ out) {
    int e   = blockIdx.z;
    int cnt = g_cnt[e];
    int m0  = blockIdx.x * BM;
    if (m0 >= cnt) return;
    int n0  = blockIdx.y * BN;

    extern __shared__ __align__(16) __half smem[];
    const int STG = ATILE + BTILE;
    __shared__ int   toks[BM];
    __shared__ float ws[BM];

    int tid = threadIdx.x;
    if (tid < BM) {
        int rr = m0 + tid;
        toks[tid] = (rr < cnt) ? g_list[e * NTOK + rr] : -1;
        ws[tid]   = (rr < cnt) ? g_lw  [e * NTOK + rr] : 0.0f;
    }
    __syncthreads();

    int arow = tid >> 1, apart = (tid & 1) * 4;
    int ra = (m0 + arow < cnt) ? arow : 0;
    int brow = tid >> 2, bpart = (tid & 3) * 2;

    const __half* pA = g_act + ((size_t)e * NTOK + m0 + ra) * FDIM + apart * 8;
    const __half* pB = g_w2t + ((size_t)e * HDIM + n0 + brow) * FDIM + bpart * 8;

    unsigned uS0 = (unsigned)__cvta_generic_to_shared(smem);
    unsigned uA = uS0 + (unsigned)(arow * AS_STR + apart * 8) * 2;
    unsigned uB = uS0 + (unsigned)(ATILE + brow * AS_STR + bpart * 8) * 2;

#define G2_ISSUE(s, kof)                                                         \
    do {                                                                         \
        unsigned sb_ = (unsigned)(s) * STG * 2;                                  \
        cpa16(uA + sb_,      pA + (kof));                                        \
        cpa16(uA + sb_ + 16, pA + (kof) + 8);                                    \
        cpa16(uA + sb_ + 32, pA + (kof) + 16);                                   \
        cpa16(uA + sb_ + 48, pA + (kof) + 24);                                   \
        cpa16(uB + sb_,      pB + (kof));                                        \
        cpa16(uB + sb_ + 16, pB + (kof) + 8);                                    \
        CP_COMMIT();                                                             \
    } while (0)

    G2_ISSUE(0, 0);
    G2_ISSUE(1, BK);

    int lane = tid & 31, warp = tid >> 5;
    int wm = warp & 3, wn = warp >> 2;
    int mb = wm * 32, nb = wn * 32;
    int r = lane >> 2, q = lane & 3;

    int lr = lane & 7, lg = lane >> 3;
    int a_row  = mb + lr + 8 * (lg & 1);
    int a_koff = 8 * (lg >> 1);
    int b_col  = nb + lr + 8 * (lg >> 1);
    int b_koff = 8 * (lg & 1);

    unsigned aoff0 = (unsigned)(a_row * AS_STR + a_koff) * 2;
    unsigned aoff1 = aoff0 + (unsigned)(16 * AS_STR) * 2;
    unsigned boff0 = (unsigned)(b_col * AS_STR + b_koff) * 2;
    unsigned boff1 = boff0 + (unsigned)(16 * AS_STR) * 2;
    const unsigned uBrel = (unsigned)ATILE * 2;

    float acc[2][4][4];
#pragma unroll
    for (int i = 0; i < 2; i++)
#pragma unroll
        for (int j = 0; j < 4; j++)
#pragma unroll
            for (int c = 0; c < 4; c++) acc[i][j][c] = 0.f;

    const int NIT = FDIM / BK;   // 64
    for (int it = 0; it < NIT; it++) {
        if (it < NIT - 1) CP_WAIT1(); else CP_WAIT0();
        __syncthreads();
        if (it + 2 < NIT) G2_ISSUE((it + 2) % NSTG, (it + 2) * BK);

        int st = it % NSTG;
        unsigned uStage = uS0 + (unsigned)(st * STG) * 2;

#pragma unroll
        for (int ks = 0; ks < 4; ks++) {
            unsigned kb = (unsigned)ks * 32u;
            unsigned af0[4], af1[4];
            LDSM4(af0[0], af0[1], af0[2], af0[3], uStage + aoff0 + kb);
            LDSM4(af1[0], af1[1], af1[2], af1[3], uStage + aoff1 + kb);
#pragma unroll
            for (int jj = 0; jj < 2; jj++) {
                unsigned bo = (jj == 0) ? boff0 : boff1;
                unsigned p0, p1, p2, p3;
                LDSM4(p0, p1, p2, p3, uStage + uBrel + bo + kb);
                MMA_F16(acc[0][2*jj],   af0[0], af0[1], af0[2], af0[3], p0, p1);
                MMA_F16(acc[1][2*jj],   af1[0], af1[1], af1[2], af1[3], p0, p1);
                MMA_F16(acc[0][2*jj+1], af0[0], af0[1], af0[2], af0[3], p2, p3);
                MMA_F16(acc[1][2*jj+1], af1[0], af1[1], af1[2], af1[3], p2, p3);
            }
        }
    }
#undef G2_ISSUE

#pragma unroll
    for (int j = 0; j < 4; j++) {
        int col = n0 + nb + 8 * j + q * 2;
        float2 bv = *(const float2*)(b2 + (size_t)e * HDIM + col);
#pragma unroll
        for (int i = 0; i < 2; i++) {
#pragma unroll
            for (int h = 0; h < 2; h++) {
                int rl = mb + 16 * i + r + 8 * h;
                int rr = m0 + rl;
                if (rr < cnt) {
                    int tok = toks[rl];
                    float w = ws[rl];
                    float* op = out + (size_t)tok * HDIM + col;
                    atomicAdd(op + 0, w * (acc[i][j][2*h+0] + bv.x));
                    atomicAdd(op + 1, w * (acc[i][j][2*h+1] + bv.y));
                }
            }
        }
    }
}

// ---------------- launch -----------------------------------------------------
extern "C" void kernel_launch(void* const* d_in, const int* in_sizes, int n_in,
                              void* d_out, int out_size) {
    const float* x     = (const float*)d_in[0];
    const float* noise = (const float*)d_in[1];
    const float* Wg    = (const float*)d_in[2];
    const float* bg    = (const float*)d_in[3];
    const float* W1    = (const float*)d_in[4];
    const float* b1    = (const float*)d_in[5];
    const float* W2    = (const float*)d_in[6];
    const float* b2    = (const float*)d_in[7];
    const float* W3    = (const float*)d_in[8];
    const float* b3    = (const float*)d_in[9];

    float* out = (float*)d_out;
    const size_t HID = (size_t)NTOK * HDIM;
    const size_t LOG = (size_t)NTOK * NEXP;
    const size_t SEL = (size_t)NTOK * TOPK;

    float* out_logits = nullptr;
    float* out_sel    = nullptr;
    if ((size_t)out_size >= HID + LOG)       out_logits = out + HID;
    if ((size_t)out_size >= HID + LOG + SEL) out_sel    = out + HID + LOG;

    // order: small/latency kernels first, then weight transpose, then GEMMs
    convert_x_kernel<<<(NTOK * HDIM / 4) / 256, 256>>>(x);
    router_kernel<<<NTOK, 128>>>(x, noise, Wg, bg, out_logits, out_sel);
    build_lists_kernel<<<1, 1024>>>();

    {
        dim3 blk(32, 8);
        dim3 g(2048, 1, 3 * NEXP);   // (K/64)*(N/32)=2048 tiles per (mat, e)
        transpose_convert_all<<<g, blk>>>(W1, W3, W2);
    }

    cudaMemsetAsync(out, 0, HID * sizeof(float));

    const int smem1 = NSTG * (ATILE + 2 * BTILE) * sizeof(__half);  // 110592
    const int smem2 = NSTG * (ATILE + BTILE) * sizeof(__half);      // 82944
    cudaFuncSetAttribute(gemm1_kernel, cudaFuncAttributeMaxDynamicSharedMemorySize, smem1);
    cudaFuncSetAttribute(gemm2_kernel, cudaFuncAttributeMaxDynamicSharedMemorySize, smem2);

    dim3 g1(NTOK / BM, FDIM / BN, NEXP);   // (16, 64, 8), M fastest
    gemm1_kernel<<<g1, 256, smem1>>>(b1, b3);

    dim3 g2(NTOK / BM, HDIM / BN, NEXP);   // (16, 16, 8)
    gemm2_kernel<<<g2, 256, smem2>>>(b2, out);
}

// round 14
// speedup vs baseline: 1.6041x; 1.6041x over previous
#include <cuda_runtime.h>
#include <cuda_fp16.h>
#include <math.h>
#include <stdint.h>

// Problem shape (fixed)
#define NTOK 2048      // B*T
#define HDIM 1024      // H
#define FDIM 4096      // F
#define NEXP 8         // E
#define TOPK 2
#define NOISE_SCALE 0.01f

// GEMM tiling
#define BM 128
#define BN 64
#define BK 64
#define AS_STR 72              // BK + 8 pad (fp16 elems); row stride 144 B (16-aligned)
#define ATILE (BM * AS_STR)    // 9216 elems
#define BTILE (BN * AS_STR)    // 4608 elems
#define NSTG 3                 // pipeline stages (prefetch distance 2)

// ---------------- device scratch (allocation-free) ---------------------------
__device__ int   g_sel[NTOK * TOPK];
__device__ float g_wt [NTOK * TOPK];
__device__ int   g_cnt[NEXP];
__device__ int   g_list[NEXP * NTOK];
__device__ float g_lw  [NEXP * NTOK];

// fp16 weights transposed to [E][N][K]; fp16 x and activations
__device__ __align__(16) __half g_w1t[(size_t)NEXP * FDIM * HDIM];
__device__ __align__(16) __half g_w3t[(size_t)NEXP * FDIM * HDIM];
__device__ __align__(16) __half g_w2t[(size_t)NEXP * HDIM * FDIM];
__device__ __align__(16) __half g_x16[(size_t)NTOK * HDIM];
__device__ __align__(16) __half g_act[(size_t)NEXP * NTOK * FDIM];

__device__ __forceinline__ float siluf(float v) { return v / (1.0f + expf(-v)); }

#define MMA_F16(d, a0,a1,a2,a3, b0,b1)                                           \
    asm volatile("mma.sync.aligned.m16n8k16.row.col.f32.f16.f16.f32 "            \
                 "{%0,%1,%2,%3},{%4,%5,%6,%7},{%8,%9},{%0,%1,%2,%3};\n"          \
                 : "+f"(d[0]), "+f"(d[1]), "+f"(d[2]), "+f"(d[3])                \
                 : "r"(a0), "r"(a1), "r"(a2), "r"(a3), "r"(b0), "r"(b1))

#define LDSM4(r0,r1,r2,r3, addr)                                                 \
    asm volatile("ldmatrix.sync.aligned.m8n8.x4.shared.b16 {%0,%1,%2,%3}, [%4];" \
                 : "=r"(r0), "=r"(r1), "=r"(r2), "=r"(r3) : "r"(addr))

__device__ __forceinline__ void cpa16(unsigned dst, const void* src) {
    asm volatile("cp.async.ca.shared.global [%0], [%1], 16;\n" :: "r"(dst), "l"(src));
}
#define CP_COMMIT() asm volatile("cp.async.commit_group;\n")
#define CP_WAIT0()  asm volatile("cp.async.wait_group 0;\n")
#define CP_WAIT1()  asm volatile("cp.async.wait_group 1;\n")

// ---------------- conversion: x fp32 -> fp16 ---------------------------------
__global__ void convert_x_kernel(const float* __restrict__ x) {
    int i = blockIdx.x * blockDim.x + threadIdx.x;   // one float4 per thread
    float4 v = reinterpret_cast<const float4*>(x)[i];
    __half2 h0 = __floats2half2_rn(v.x, v.y);
    __half2 h1 = __floats2half2_rn(v.z, v.w);
    uint2 o;
    o.x = *reinterpret_cast<unsigned*>(&h0);
    o.y = *reinterpret_cast<unsigned*>(&h1);
    reinterpret_cast<uint2*>(g_x16)[i] = o;
}

// ---------------- fused transpose+convert for W1, W3, W2 ---------------------
// W[e][K][N] f32 -> Wt[e][N][K] fp16; tile 64(k) x 32(n); 128B coalesced stores.
__global__ void transpose_convert_all(const float* __restrict__ W1,
                                      const float* __restrict__ W3,
                                      const float* __restrict__ W2) {
    __shared__ float tile[64][33];
    int z = blockIdx.z;
    int mat = z >> 3;          // 0:W1, 1:W3, 2:W2
    int e   = z & 7;
    const float* W;
    __half* Wt;
    int K, N;
    if (mat == 0)      { W = W1; Wt = g_w1t; K = HDIM; N = FDIM; }
    else if (mat == 1) { W = W3; Wt = g_w3t; K = HDIM; N = FDIM; }
    else               { W = W2; Wt = g_w2t; K = FDIM; N = HDIM; }

    int ntn = N >> 5;
    int n0 = (blockIdx.x % ntn) << 5;
    int k0 = (blockIdx.x / ntn) << 6;

    const float* We = W + (size_t)e * K * N;
    int tx = threadIdx.x, ty = threadIdx.y;   // 32 x 8
#pragma unroll
    for (int j = 0; j < 64; j += 8)
        tile[ty + j][tx] = We[(size_t)(k0 + ty + j) * N + n0 + tx];
    __syncthreads();
    size_t base = (size_t)e * K * N;
#pragma unroll
    for (int j = 0; j < 32; j += 8) {
        int n = ty + j;
        __half2 hv = __floats2half2_rn(tile[2 * tx][n], tile[2 * tx + 1][n]);
        *(__half2*)&Wt[base + (size_t)(n0 + n) * K + k0 + 2 * tx] = hv;
    }
}

// ---------------- router -----------------------------------------------------
__global__ void router_kernel(const float* __restrict__ x,
                              const float* __restrict__ noise,
                              const float* __restrict__ Wg,
                              const float* __restrict__ bg,
                              float* out_logits, float* out_sel) {
    int n = blockIdx.x;
    int tid = threadIdx.x;          // 128
    const float* xr = x + (size_t)n * HDIM;

    float acc[NEXP];
#pragma unroll
    for (int e = 0; e < NEXP; e++) acc[e] = 0.0f;
    for (int h = tid; h < HDIM; h += 128) {
        float xv = xr[h];
        const float* wr = Wg + (size_t)h * NEXP;
#pragma unroll
        for (int e = 0; e < NEXP; e++) acc[e] += xv * wr[e];
    }

    __shared__ float red[NEXP][128];
#pragma unroll
    for (int e = 0; e < NEXP; e++) red[e][tid] = acc[e];
    __syncthreads();
    for (int s = 64; s > 0; s >>= 1) {
        if (tid < s) {
#pragma unroll
            for (int e = 0; e < NEXP; e++) red[e][tid] += red[e][tid + s];
        }
        __syncthreads();
    }

    if (tid == 0) {
        float l[NEXP];
#pragma unroll
        for (int e = 0; e < NEXP; e++)
            l[e] = red[e][0] + bg[e] + NOISE_SCALE * noise[(size_t)n * NEXP + e];
        if (out_logits) {
#pragma unroll
            for (int e = 0; e < NEXP; e++)
                out_logits[(size_t)n * NEXP + e] = l[e];
        }
        int i0 = 0;
#pragma unroll
        for (int e = 1; e < NEXP; e++) if (l[e] > l[i0]) i0 = e;
        int i1 = (i0 == 0) ? 1 : 0;
#pragma unroll
        for (int e = 0; e < NEXP; e++) if (e != i0 && l[e] > l[i1]) i1 = e;

        float r = expf(l[i1] - l[i0]);
        float w0 = 1.0f / (1.0f + r);
        float w1 = r / (1.0f + r);
        g_sel[n * TOPK + 0] = i0;
        g_sel[n * TOPK + 1] = i1;
        g_wt [n * TOPK + 0] = w0;
        g_wt [n * TOPK + 1] = w1;
        if (out_sel) {
            out_sel[n * TOPK + 0] = (float)i0;
            out_sel[n * TOPK + 1] = (float)i1;
        }
    }
}

// ---------------- stable per-expert compaction (parallel) --------------------
#define BL_CHUNK (NTOK / 4)            // 512 tokens per chunk
#define BL_ITER  (BL_CHUNK / 32)       // 16 ballots per warp
__global__ void build_lists_kernel() {
    __shared__ int      cnt_sh[NEXP][4];
    __shared__ unsigned mk_any[32][BL_ITER];
    __shared__ unsigned mk_m0 [32][BL_ITER];

    int tid = threadIdx.x, lane = tid & 31, w = tid >> 5;
    int e = w & 7, c = w >> 3;
    int tok0 = c * BL_CHUNK;

    int cc = 0;
#pragma unroll
    for (int i = 0; i < BL_ITER; i++) {
        int n = tok0 + i * 32 + lane;
        int s0 = g_sel[n * TOPK + 0];
        int s1 = g_sel[n * TOPK + 1];
        bool m0 = (s0 == e), m1 = (s1 == e);
        unsigned ma = __ballot_sync(0xffffffffu, m0 || m1);
        unsigned mz = __ballot_sync(0xffffffffu, m0);
        if (lane == 0) { mk_any[w][i] = ma; mk_m0[w][i] = mz; }
        cc += __popc(ma);
    }
    if (lane == 0) cnt_sh[e][c] = cc;
    __syncthreads();

    int base = 0;
#pragma unroll
    for (int k = 0; k < 4; k++) {
        if (k < c) base += cnt_sh[e][k];
    }
    if (c == 3 && lane == 0) g_cnt[e] = base + cnt_sh[e][3];

    int run = base;
#pragma unroll
    for (int i = 0; i < BL_ITER; i++) {
        unsigned ma = mk_any[w][i];
        unsigned mz = mk_m0[w][i];
        int n = tok0 + i * 32 + lane;
        if (ma & (1u << lane)) {
            int pos = run + __popc(ma & ((1u << lane) - 1u));
            g_list[e * NTOK + pos] = n;
            bool is0 = (mz >> lane) & 1u;
            g_lw[e * NTOK + pos] = g_wt[n * TOPK + (is0 ? 0 : 1)];
        }
        run += __popc(ma);
    }
}

// ---------------- GEMM1 (fp16 mma + ldmatrix), 512 threads -------------------
// grid: (m=16, n=64, e=8). 16 warps: 4m x 4n, each warp 32x16 outputs.
// acc = 2x[2][2][4] = 32 regs/warp -> no spills; 4 warps/SMSP latency hiding.
__global__ __launch_bounds__(512, 1)
void gemm1_kernel(const float* __restrict__ b1, const float* __restrict__ b3) {
    int e   = blockIdx.z;
    int cnt = g_cnt[e];
    int m0  = blockIdx.x * BM;
    if (m0 >= cnt) return;
    int n0  = blockIdx.y * BN;

    extern __shared__ __align__(16) __half smem[];
    const int STG = ATILE + 2 * BTILE;    // halves per stage
    __shared__ int toks[BM];

    int tid = threadIdx.x;
    if (tid < BM) {
        int r = m0 + tid;
        toks[tid] = (r < cnt) ? g_list[e * NTOK + r] : -1;
    }
    __syncthreads();

    // staging: per thread 2 A chunks + 2 B chunks (16B each).
    int arow = tid >> 2, apart = (tid & 3) * 2;
    int tokA = toks[arow]; if (tokA < 0) tokA = 0;
    int browv = tid >> 2;
    bool isW3 = (browv >= 64);
    int brow = browv & 63;
    int bpart = (tid & 3) * 2;

    const __half* pA = g_x16 + (size_t)tokA * HDIM + apart * 8;
    const __half* pB = (isW3 ? g_w3t : g_w1t)
                       + ((size_t)e * FDIM + n0 + brow) * HDIM + bpart * 8;

    unsigned uS0 = (unsigned)__cvta_generic_to_shared(smem);
    unsigned uA = uS0 + (unsigned)(arow * AS_STR + apart * 8) * 2;
    unsigned uB = uS0 + (unsigned)((isW3 ? (ATILE + BTILE) : ATILE)
                                   + brow * AS_STR + bpart * 8) * 2;

#define G1_ISSUE(s, kof)                                                         \
    do {                                                                         \
        unsigned sb_ = (unsigned)(s) * STG * 2;                                  \
        cpa16(uA + sb_,      pA + (kof));                                        \
        cpa16(uA + sb_ + 16, pA + (kof) + 8);                                    \
        cpa16(uB + sb_,      pB + (kof));                                        \
        cpa16(uB + sb_ + 16, pB + (kof) + 8);                                    \
        CP_COMMIT();                                                             \
    } while (0)

    // preload stages 0,1 (iterations 0,1)
    G1_ISSUE(0, 0);
    G1_ISSUE(1, BK);

    int lane = tid & 31, warp = tid >> 5;   // 16 warps
    int wm = warp & 3, wn = warp >> 2;      // 4m x 4n
    int mb = wm * 32, nb = wn * 16;
    int r = lane >> 2, q = lane & 3;

    // ldmatrix lane addressing (4 groups of 8 lanes)
    int lr = lane & 7, lg = lane >> 3;
    int a_row  = mb + lr + 8 * (lg & 1);
    int a_koff = 8 * (lg >> 1);
    int b_col  = nb + lr + 8 * (lg >> 1);
    int b_koff = 8 * (lg & 1);

    unsigned aoff0 = (unsigned)(a_row * AS_STR + a_koff) * 2;            // A region rel
    unsigned aoff1 = aoff0 + (unsigned)(16 * AS_STR) * 2;
    unsigned boff0 = (unsigned)(b_col * AS_STR + b_koff) * 2;            // B region rel
    const unsigned uB1rel = (unsigned)ATILE * 2;
    const unsigned uB3rel = (unsigned)(ATILE + BTILE) * 2;

    float acc1[2][2][4], acc3[2][2][4];
#pragma unroll
    for (int i = 0; i < 2; i++)
#pragma unroll
        for (int j = 0; j < 2; j++)
#pragma unroll
            for (int c = 0; c < 4; c++) { acc1[i][j][c] = 0.f; acc3[i][j][c] = 0.f; }

    const int NIT = HDIM / BK;   // 16
    for (int it = 0; it < NIT; it++) {
        if (it < NIT - 1) CP_WAIT1(); else CP_WAIT0();
        __syncthreads();
        // prefetch it+2 into stage (it+2)%3: last READ at it-1; sync above orders it.
        if (it + 2 < NIT) G1_ISSUE((it + 2) % NSTG, (it + 2) * BK);

        int st = it % NSTG;
        unsigned uStage = uS0 + (unsigned)(st * STG) * 2;

#pragma unroll
        for (int ks = 0; ks < 4; ks++) {
            unsigned kb = (unsigned)ks * 32u;
            unsigned af0[4], af1[4];
            LDSM4(af0[0], af0[1], af0[2], af0[3], uStage + aoff0 + kb);
            LDSM4(af1[0], af1[1], af1[2], af1[3], uStage + aoff1 + kb);
            unsigned p0, p1, p2, p3;
            LDSM4(p0, p1, p2, p3, uStage + uB1rel + boff0 + kb);
            MMA_F16(acc1[0][0], af0[0], af0[1], af0[2], af0[3], p0, p1);
            MMA_F16(acc1[1][0], af1[0], af1[1], af1[2], af1[3], p0, p1);
            MMA_F16(acc1[0][1], af0[0], af0[1], af0[2], af0[3], p2, p3);
            MMA_F16(acc1[1][1], af1[0], af1[1], af1[2], af1[3], p2, p3);
            unsigned t0, t1, t2, t3;
            LDSM4(t0, t1, t2, t3, uStage + uB3rel + boff0 + kb);
            MMA_F16(acc3[0][0], af0[0], af0[1], af0[2], af0[3], t0, t1);
            MMA_F16(acc3[1][0], af1[0], af1[1], af1[2], af1[3], t0, t1);
            MMA_F16(acc3[0][1], af0[0], af0[1], af0[2], af0[3], t2, t3);
            MMA_F16(acc3[1][1], af1[0], af1[1], af1[2], af1[3], t2, t3);
        }
    }
#undef G1_ISSUE

    // epilogue: silu(h)*g -> fp16 act (each warp: 32 rows x 16 cols)
#pragma unroll
    for (int j = 0; j < 2; j++) {
        int col = n0 + nb + 8 * j + q * 2;
        float2 bv1 = *(const float2*)(b1 + (size_t)e * FDIM + col);
        float2 bv3 = *(const float2*)(b3 + (size_t)e * FDIM + col);
#pragma unroll
        for (int i = 0; i < 2; i++) {
#pragma unroll
            for (int h = 0; h < 2; h++) {
                int rl = mb + 16 * i + r + 8 * h;
                int rr = m0 + rl;
                if (rr < cnt) {
                    float v0 = siluf(acc1[i][j][2*h+0] + bv1.x) * (acc3[i][j][2*h+0] + bv3.x);
                    float v1 = siluf(acc1[i][j][2*h+1] + bv1.y) * (acc3[i][j][2*h+1] + bv3.y);
                    __half2 hv = __floats2half2_rn(v0, v1);
                    *(__half2*)(g_act + ((size_t)e * NTOK + rr) * FDIM + col) = hv;
                }
            }
        }
    }
}

// ---------------- GEMM2 (fp16 mma + ldmatrix): out[tok] += w * (act@W2 + b2) -
// grid: (m=16, n=16, e=8), 256 threads, 3-stage pipeline, 2 CTAs/SM (R11 config)
__global__ __launch_bounds__(256, 2)
void gemm2_kernel(const float* __restrict__ b2, float* __restrict__ out) {
    int e   = blockIdx.z;
    int cnt = g_cnt[e];
    int m0  = blockIdx.x * BM;
    if (m0 >= cnt) return;
    int n0  = blockIdx.y * BN;

    extern __shared__ __align__(16) __half smem[];
    const int STG = ATILE + BTILE;
    __shared__ int   toks[BM];
    __shared__ float ws[BM];

    int tid = threadIdx.x;
    if (tid < BM) {
        int rr = m0 + tid;
        toks[tid] = (rr < cnt) ? g_list[e * NTOK + rr] : -1;
        ws[tid]   = (rr < cnt) ? g_lw  [e * NTOK + rr] : 0.0f;
    }
    __syncthreads();

    int arow = tid >> 1, apart = (tid & 1) * 4;
    int ra = (m0 + arow < cnt) ? arow : 0;
    int brow = tid >> 2, bpart = (tid & 3) * 2;

    const __half* pA = g_act + ((size_t)e * NTOK + m0 + ra) * FDIM + apart * 8;
    const __half* pB = g_w2t + ((size_t)e * HDIM + n0 + brow) * FDIM + bpart * 8;

    unsigned uS0 = (unsigned)__cvta_generic_to_shared(smem);
    unsigned uA = uS0 + (unsigned)(arow * AS_STR + apart * 8) * 2;
    unsigned uB = uS0 + (unsigned)(ATILE + brow * AS_STR + bpart * 8) * 2;

#define G2_ISSUE(s, kof)                                                         \
    do {                                                                         \
        unsigned sb_ = (unsigned)(s) * STG * 2;                                  \
        cpa16(uA + sb_,      pA + (kof));                                        \
        cpa16(uA + sb_ + 16, pA + (kof) + 8);                                    \
        cpa16(uA + sb_ + 32, pA + (kof) + 16);                                   \
        cpa16(uA + sb_ + 48, pA + (kof) + 24);                                   \
        cpa16(uB + sb_,      pB + (kof));                                        \
        cpa16(uB + sb_ + 16, pB + (kof) + 8);                                    \
        CP_COMMIT();                                                             \
    } while (0)

    G2_ISSUE(0, 0);
    G2_ISSUE(1, BK);

    int lane = tid & 31, warp = tid >> 5;
    int wm = warp & 3, wn = warp >> 2;
    int mb = wm * 32, nb = wn * 32;
    int r = lane >> 2, q = lane & 3;

    int lr = lane & 7, lg = lane >> 3;
    int a_row  = mb + lr + 8 * (lg & 1);
    int a_koff = 8 * (lg >> 1);
    int b_col  = nb + lr + 8 * (lg >> 1);
    int b_koff = 8 * (lg & 1);

    unsigned aoff0 = (unsigned)(a_row * AS_STR + a_koff) * 2;
    unsigned aoff1 = aoff0 + (unsigned)(16 * AS_STR) * 2;
    unsigned boff0 = (unsigned)(b_col * AS_STR + b_koff) * 2;
    unsigned boff1 = boff0 + (unsigned)(16 * AS_STR) * 2;
    const unsigned uBrel = (unsigned)ATILE * 2;

    float acc[2][4][4];
#pragma unroll
    for (int i = 0; i < 2; i++)
#pragma unroll
        for (int j = 0; j < 4; j++)
#pragma unroll
            for (int c = 0; c < 4; c++) acc[i][j][c] = 0.f;

    const int NIT = FDIM / BK;   // 64
    for (int it = 0; it < NIT; it++) {
        if (it < NIT - 1) CP_WAIT1(); else CP_WAIT0();
        __syncthreads();
        if (it + 2 < NIT) G2_ISSUE((it + 2) % NSTG, (it + 2) * BK);

        int st = it % NSTG;
        unsigned uStage = uS0 + (unsigned)(st * STG) * 2;

#pragma unroll
        for (int ks = 0; ks < 4; ks++) {
            unsigned kb = (unsigned)ks * 32u;
            unsigned af0[4], af1[4];
            LDSM4(af0[0], af0[1], af0[2], af0[3], uStage + aoff0 + kb);
            LDSM4(af1[0], af1[1], af1[2], af1[3], uStage + aoff1 + kb);
#pragma unroll
            for (int jj = 0; jj < 2; jj++) {
                unsigned bo = (jj == 0) ? boff0 : boff1;
                unsigned p0, p1, p2, p3;
                LDSM4(p0, p1, p2, p3, uStage + uBrel + bo + kb);
                MMA_F16(acc[0][2*jj],   af0[0], af0[1], af0[2], af0[3], p0, p1);
                MMA_F16(acc[1][2*jj],   af1[0], af1[1], af1[2], af1[3], p0, p1);
                MMA_F16(acc[0][2*jj+1], af0[0], af0[1], af0[2], af0[3], p2, p3);
                MMA_F16(acc[1][2*jj+1], af1[0], af1[1], af1[2], af1[3], p2, p3);
            }
        }
    }
#undef G2_ISSUE

#pragma unroll
    for (int j = 0; j < 4; j++) {
        int col = n0 + nb + 8 * j + q * 2;
        float2 bv = *(const float2*)(b2 + (size_t)e * HDIM + col);
#pragma unroll
        for (int i = 0; i < 2; i++) {
#pragma unroll
            for (int h = 0; h < 2; h++) {
                int rl = mb + 16 * i + r + 8 * h;
                int rr = m0 + rl;
                if (rr < cnt) {
                    int tok = toks[rl];
                    float w = ws[rl];
                    float* op = out + (size_t)tok * HDIM + col;
                    atomicAdd(op + 0, w * (acc[i][j][2*h+0] + bv.x));
                    atomicAdd(op + 1, w * (acc[i][j][2*h+1] + bv.y));
                }
            }
        }
    }
}

// ---------------- launch -----------------------------------------------------
extern "C" void kernel_launch(void* const* d_in, const int* in_sizes, int n_in,
                              void* d_out, int out_size) {
    const float* x     = (const float*)d_in[0];
    const float* noise = (const float*)d_in[1];
    const float* Wg    = (const float*)d_in[2];
    const float* bg    = (const float*)d_in[3];
    const float* W1    = (const float*)d_in[4];
    const float* b1    = (const float*)d_in[5];
    const float* W2    = (const float*)d_in[6];
    const float* b2    = (const float*)d_in[7];
    const float* W3    = (const float*)d_in[8];
    const float* b3    = (const float*)d_in[9];

    float* out = (float*)d_out;
    const size_t HID = (size_t)NTOK * HDIM;
    const size_t LOG = (size_t)NTOK * NEXP;
    const size_t SEL = (size_t)NTOK * TOPK;

    float* out_logits = nullptr;
    float* out_sel    = nullptr;
    if ((size_t)out_size >= HID + LOG)       out_logits = out + HID;
    if ((size_t)out_size >= HID + LOG + SEL) out_sel    = out + HID + LOG;

    convert_x_kernel<<<(NTOK * HDIM / 4) / 256, 256>>>(x);
    router_kernel<<<NTOK, 128>>>(x, noise, Wg, bg, out_logits, out_sel);
    build_lists_kernel<<<1, 1024>>>();

    {
        dim3 blk(32, 8);
        dim3 g(2048, 1, 3 * NEXP);   // (K/64)*(N/32)=2048 tiles per (mat, e)
        transpose_convert_all<<<g, blk>>>(W1, W3, W2);
    }

    cudaMemsetAsync(out, 0, HID * sizeof(float));

    const int smem1 = NSTG * (ATILE + 2 * BTILE) * sizeof(__half);  // 110592
    const int smem2 = NSTG * (ATILE + BTILE) * sizeof(__half);      // 82944
    cudaFuncSetAttribute(gemm1_kernel, cudaFuncAttributeMaxDynamicSharedMemorySize, smem1);
    cudaFuncSetAttribute(gemm2_kernel, cudaFuncAttributeMaxDynamicSharedMemorySize, smem2);

    dim3 g1(NTOK / BM, FDIM / BN, NEXP);   // (16, 64, 8), M fastest
    gemm1_kernel<<<g1, 512, smem1>>>(b1, b3);

    dim3 g2(NTOK / BM, HDIM / BN, NEXP);   // (16, 16, 8)
    gemm2_kernel<<<g2, 256, smem2>>>(b2, out);
}

// round 15
// speedup vs baseline: 1.6196x; 1.0097x over previous
#include <cuda_runtime.h>
#include <cuda_fp16.h>
#include <math.h>
#include <stdint.h>

// Problem shape (fixed)
#define NTOK 2048      // B*T
#define HDIM 1024      // H
#define FDIM 4096      // F
#define NEXP 8         // E
#define TOPK 2
#define NOISE_SCALE 0.01f

// GEMM tiling
#define BM 128
#define BN 64
#define BK 64
#define AS_STR 72              // stride (fp16 elems); row stride 144 B
#define ATILE (BM * AS_STR)    // 9216 elems
#define BTILE (BK * AS_STR)    // 4608 elems (B tile: 64 k-rows x 72)
#define NSTG 3                 // pipeline stages (prefetch distance 2)

// ---------------- device scratch (allocation-free) ---------------------------
__device__ int   g_sel[NTOK * TOPK];
__device__ float g_wt [NTOK * TOPK];
__device__ int   g_cnt[NEXP];
__device__ int   g_list[NEXP * NTOK];
__device__ float g_lw  [NEXP * NTOK];

__device__ __align__(16) __half g_x16[(size_t)NTOK * HDIM];
__device__ __align__(16) __half g_act[(size_t)NEXP * NTOK * FDIM];

__device__ __forceinline__ float siluf(float v) { return v / (1.0f + expf(-v)); }

__device__ __forceinline__ unsigned pack2h(float a, float b) {
    __half2 h = __floats2half2_rn(a, b);
    return *reinterpret_cast<unsigned*>(&h);
}

#define MMA_F16(d, a0,a1,a2,a3, b0,b1)                                           \
    asm volatile("mma.sync.aligned.m16n8k16.row.col.f32.f16.f16.f32 "            \
                 "{%0,%1,%2,%3},{%4,%5,%6,%7},{%8,%9},{%0,%1,%2,%3};\n"          \
                 : "+f"(d[0]), "+f"(d[1]), "+f"(d[2]), "+f"(d[3])                \
                 : "r"(a0), "r"(a1), "r"(a2), "r"(a3), "r"(b0), "r"(b1))

#define LDSM4(r0,r1,r2,r3, addr)                                                 \
    asm volatile("ldmatrix.sync.aligned.m8n8.x4.shared.b16 {%0,%1,%2,%3}, [%4];" \
                 : "=r"(r0), "=r"(r1), "=r"(r2), "=r"(r3) : "r"(addr))

#define LDSM4T(r0,r1,r2,r3, addr)                                                \
    asm volatile("ldmatrix.sync.aligned.m8n8.x4.trans.shared.b16 {%0,%1,%2,%3}, [%4];" \
                 : "=r"(r0), "=r"(r1), "=r"(r2), "=r"(r3) : "r"(addr))

__device__ __forceinline__ void cpa16(unsigned dst, const void* src) {
    asm volatile("cp.async.ca.shared.global [%0], [%1], 16;\n" :: "r"(dst), "l"(src));
}
#define CP_COMMIT() asm volatile("cp.async.commit_group;\n")
#define CP_WAIT0()  asm volatile("cp.async.wait_group 0;\n")
#define CP_WAIT1()  asm volatile("cp.async.wait_group 1;\n")

// ---------------- conversion: x fp32 -> fp16 ---------------------------------
__global__ void convert_x_kernel(const float* __restrict__ x) {
    int i = blockIdx.x * blockDim.x + threadIdx.x;
    float4 v = reinterpret_cast<const float4*>(x)[i];
    uint2 o;
    o.x = pack2h(v.x, v.y);
    o.y = pack2h(v.z, v.w);
    reinterpret_cast<uint2*>(g_x16)[i] = o;
}

// ---------------- router -----------------------------------------------------
__global__ void router_kernel(const float* __restrict__ x,
                              const float* __restrict__ noise,
                              const float* __restrict__ Wg,
                              const float* __restrict__ bg,
                              float* out_logits, float* out_sel) {
    int n = blockIdx.x;
    int tid = threadIdx.x;          // 128
    const float* xr = x + (size_t)n * HDIM;

    float acc[NEXP];
#pragma unroll
    for (int e = 0; e < NEXP; e++) acc[e] = 0.0f;
    for (int h = tid; h < HDIM; h += 128) {
        float xv = xr[h];
        const float* wr = Wg + (size_t)h * NEXP;
#pragma unroll
        for (int e = 0; e < NEXP; e++) acc[e] += xv * wr[e];
    }

    __shared__ float red[NEXP][128];
#pragma unroll
    for (int e = 0; e < NEXP; e++) red[e][tid] = acc[e];
    __syncthreads();
    for (int s = 64; s > 0; s >>= 1) {
        if (tid < s) {
#pragma unroll
            for (int e = 0; e < NEXP; e++) red[e][tid] += red[e][tid + s];
        }
        __syncthreads();
    }

    if (tid == 0) {
        float l[NEXP];
#pragma unroll
        for (int e = 0; e < NEXP; e++)
            l[e] = red[e][0] + bg[e] + NOISE_SCALE * noise[(size_t)n * NEXP + e];
        if (out_logits) {
#pragma unroll
            for (int e = 0; e < NEXP; e++)
                out_logits[(size_t)n * NEXP + e] = l[e];
        }
        int i0 = 0;
#pragma unroll
        for (int e = 1; e < NEXP; e++) if (l[e] > l[i0]) i0 = e;
        int i1 = (i0 == 0) ? 1 : 0;
#pragma unroll
        for (int e = 0; e < NEXP; e++) if (e != i0 && l[e] > l[i1]) i1 = e;

        float r = expf(l[i1] - l[i0]);
        float w0 = 1.0f / (1.0f + r);
        float w1 = r / (1.0f + r);
        g_sel[n * TOPK + 0] = i0;
        g_sel[n * TOPK + 1] = i1;
        g_wt [n * TOPK + 0] = w0;
        g_wt [n * TOPK + 1] = w1;
        if (out_sel) {
            out_sel[n * TOPK + 0] = (float)i0;
            out_sel[n * TOPK + 1] = (float)i1;
        }
    }
}

// ---------------- stable per-expert compaction (parallel) --------------------
#define BL_CHUNK (NTOK / 4)            // 512 tokens per chunk
#define BL_ITER  (BL_CHUNK / 32)       // 16 ballots per warp
__global__ void build_lists_kernel() {
    __shared__ int      cnt_sh[NEXP][4];
    __shared__ unsigned mk_any[32][BL_ITER];
    __shared__ unsigned mk_m0 [32][BL_ITER];

    int tid = threadIdx.x, lane = tid & 31, w = tid >> 5;
    int e = w & 7, c = w >> 3;
    int tok0 = c * BL_CHUNK;

    int cc = 0;
#pragma unroll
    for (int i = 0; i < BL_ITER; i++) {
        int n = tok0 + i * 32 + lane;
        int s0 = g_sel[n * TOPK + 0];
        int s1 = g_sel[n * TOPK + 1];
        bool m0 = (s0 == e), m1 = (s1 == e);
        unsigned ma = __ballot_sync(0xffffffffu, m0 || m1);
        unsigned mz = __ballot_sync(0xffffffffu, m0);
        if (lane == 0) { mk_any[w][i] = ma; mk_m0[w][i] = mz; }
        cc += __popc(ma);
    }
    if (lane == 0) cnt_sh[e][c] = cc;
    __syncthreads();

    int base = 0;
#pragma unroll
    for (int k = 0; k < 4; k++) {
        if (k < c) base += cnt_sh[e][k];
    }
    if (c == 3 && lane == 0) g_cnt[e] = base + cnt_sh[e][3];

    int run = base;
#pragma unroll
    for (int i = 0; i < BL_ITER; i++) {
        unsigned ma = mk_any[w][i];
        unsigned mz = mk_m0[w][i];
        int n = tok0 + i * 32 + lane;
        if (ma & (1u << lane)) {
            int pos = run + __popc(ma & ((1u << lane) - 1u));
            g_list[e * NTOK + pos] = n;
            bool is0 = (mz >> lane) & 1u;
            g_lw[e * NTOK + pos] = g_wt[n * TOPK + (is0 ? 0 : 1)];
        }
        run += __popc(ma);
    }
}

// ---------------- GEMM1, 512 threads, fused weight convert -------------------
// B tiles staged straight from fp32 W1/W3 [H][F]: LDG f32 (coalesced along F),
// convert in regs, STS fp16 [k][n] tile, ldmatrix.x4.trans for fragments.
// A via cp.async from g_x16 (3-stage). 16 warps: 4m x 4n, 32x16 outputs each.
__global__ __launch_bounds__(512, 1)
void gemm1_kernel(const float* __restrict__ W1, const float* __restrict__ b1,
                  const float* __restrict__ W3, const float* __restrict__ b3) {
    int e   = blockIdx.z;
    int cnt = g_cnt[e];
    int m0  = blockIdx.x * BM;
    if (m0 >= cnt) return;
    int n0  = blockIdx.y * BN;

    extern __shared__ __align__(16) __half smem[];
    const int STG = ATILE + 2 * BTILE;    // halves per stage
    __shared__ int toks[BM];

    int tid = threadIdx.x;
    if (tid < BM) {
        int r = m0 + tid;
        toks[tid] = (r < cnt) ? g_list[e * NTOK + r] : -1;
    }
    __syncthreads();

    // A staging: 1024 chunks / 512 threads = 2 cp.async per thread
    int arow = tid >> 2, apart = (tid & 3) * 2;
    int tokA = toks[arow]; if (tokA < 0) tokA = 0;
    const __half* pA = g_x16 + (size_t)tokA * HDIM + apart * 8;

    unsigned uS0 = (unsigned)__cvta_generic_to_shared(smem);
    unsigned uA = uS0 + (unsigned)(arow * AS_STR + apart * 8) * 2;

    // B staging: tile [64 k][64 n]; 8 threads/row x 8 f32 each, for W1 and W3
    int bkrow = tid >> 3;            // 0..63
    int bnoff = (tid & 7) * 8;       // 0..56
    const float* pW1 = W1 + (size_t)e * HDIM * FDIM + (size_t)bkrow * FDIM + n0 + bnoff;
    const float* pW3 = W3 + (size_t)e * HDIM * FDIM + (size_t)bkrow * FDIM + n0 + bnoff;
    int bsts = bkrow * AS_STR + bnoff;   // elem offset within B region

    float4 rb1a, rb1b, rb3a, rb3b;

#define G1_LDGB(kof)                                                             \
    do {                                                                         \
        const float* b1p_ = pW1 + (size_t)(kof) * FDIM;                          \
        rb1a = *(const float4*)(b1p_);                                           \
        rb1b = *(const float4*)(b1p_ + 4);                                       \
        const float* b3p_ = pW3 + (size_t)(kof) * FDIM;                          \
        rb3a = *(const float4*)(b3p_);                                           \
        rb3b = *(const float4*)(b3p_ + 4);                                       \
    } while (0)

#define G1_STSB(s)                                                               \
    do {                                                                         \
        uint4 u_;                                                                \
        u_.x = pack2h(rb1a.x, rb1a.y); u_.y = pack2h(rb1a.z, rb1a.w);            \
        u_.z = pack2h(rb1b.x, rb1b.y); u_.w = pack2h(rb1b.z, rb1b.w);            \
        *(uint4*)(smem + (s) * STG + ATILE + bsts) = u_;                         \
        u_.x = pack2h(rb3a.x, rb3a.y); u_.y = pack2h(rb3a.z, rb3a.w);            \
        u_.z = pack2h(rb3b.x, rb3b.y); u_.w = pack2h(rb3b.z, rb3b.w);            \
        *(uint4*)(smem + (s) * STG + ATILE + BTILE + bsts) = u_;                 \
    } while (0)

#define G1_ISSUEA(s, kof)                                                        \
    do {                                                                         \
        unsigned sb_ = (unsigned)(s) * STG * 2;                                  \
        cpa16(uA + sb_,      pA + (kof));                                        \
        cpa16(uA + sb_ + 16, pA + (kof) + 8);                                    \
        CP_COMMIT();                                                             \
    } while (0)

    // prologue: B(0) -> smem slot0; regs <- B(1); A(0),A(1) in flight
    G1_LDGB(0);
    G1_STSB(0);
    G1_LDGB(BK);
    G1_ISSUEA(0, 0);
    G1_ISSUEA(1, BK);

    int lane = tid & 31, warp = tid >> 5;   // 16 warps
    int wm = warp & 3, wn = warp >> 2;      // 4m x 4n
    int mb = wm * 32, nb = wn * 16;
    int r = lane >> 2, q = lane & 3;

    int lr = lane & 7, lg = lane >> 3;
    // A (non-trans): row-major [m][k]
    int a_row  = mb + lr + 8 * (lg & 1);
    int a_koff = 8 * (lg >> 1);
    unsigned aoff0 = (unsigned)(a_row * AS_STR + a_koff) * 2;
    unsigned aoff1 = aoff0 + (unsigned)(16 * AS_STR) * 2;
    // B (trans): [k][n]; m0=(k0..7,nb) m1=(k8..15,nb) m2=(k0..7,nb+8) m3=(k8..15,nb+8)
    unsigned bT = (unsigned)((8 * (lg & 1) + lr) * AS_STR + nb + 8 * (lg >> 1)) * 2;
    const unsigned uB1rel = (unsigned)ATILE * 2;
    const unsigned uB3rel = (unsigned)(ATILE + BTILE) * 2;

    float acc1[2][2][4], acc3[2][2][4];
#pragma unroll
    for (int i = 0; i < 2; i++)
#pragma unroll
        for (int j = 0; j < 2; j++)
#pragma unroll
            for (int c = 0; c < 4; c++) { acc1[i][j][c] = 0.f; acc3[i][j][c] = 0.f; }

    const int NIT = HDIM / BK;   // 16
    for (int it = 0; it < NIT; it++) {
        if (it < NIT - 1) CP_WAIT1(); else CP_WAIT0();
        __syncthreads();
        // B(it+1) STS into slot (it+1)%3: last read at it-2; sync above orders it.
        if (it + 1 < NIT) G1_STSB((it + 1) % NSTG);
        if (it + 2 < NIT) {
            G1_LDGB((it + 2) * BK);
            G1_ISSUEA((it + 2) % NSTG, (it + 2) * BK);
        }

        int st = it % NSTG;
        unsigned uStage = uS0 + (unsigned)(st * STG) * 2;

#pragma unroll
        for (int ks = 0; ks < 4; ks++) {
            unsigned kbA = (unsigned)ks * 32u;                        // A: +16 k = 32 B
            unsigned kbB = (unsigned)ks * (16u * AS_STR * 2u);        // B: +16 rows
            unsigned af0[4], af1[4];
            LDSM4(af0[0], af0[1], af0[2], af0[3], uStage + aoff0 + kbA);
            LDSM4(af1[0], af1[1], af1[2], af1[3], uStage + aoff1 + kbA);
            unsigned p0, p1, p2, p3;
            LDSM4T(p0, p1, p2, p3, uStage + uB1rel + bT + kbB);
            MMA_F16(acc1[0][0], af0[0], af0[1], af0[2], af0[3], p0, p1);
            MMA_F16(acc1[1][0], af1[0], af1[1], af1[2], af1[3], p0, p1);
            MMA_F16(acc1[0][1], af0[0], af0[1], af0[2], af0[3], p2, p3);
            MMA_F16(acc1[1][1], af1[0], af1[1], af1[2], af1[3], p2, p3);
            unsigned t0, t1, t2, t3;
            LDSM4T(t0, t1, t2, t3, uStage + uB3rel + bT + kbB);
            MMA_F16(acc3[0][0], af0[0], af0[1], af0[2], af0[3], t0, t1);
            MMA_F16(acc3[1][0], af1[0], af1[1], af1[2], af1[3], t0, t1);
            MMA_F16(acc3[0][1], af0[0], af0[1], af0[2], af0[3], t2, t3);
            MMA_F16(acc3[1][1], af1[0], af1[1], af1[2], af1[3], t2, t3);
        }
    }
#undef G1_LDGB
#undef G1_STSB
#undef G1_ISSUEA

    // epilogue: silu(h)*g -> fp16 act (each warp: 32 rows x 16 cols)
#pragma unroll
    for (int j = 0; j < 2; j++) {
        int col = n0 + nb + 8 * j + q * 2;
        float2 bv1 = *(const float2*)(b1 + (size_t)e * FDIM + col);
        float2 bv3 = *(const float2*)(b3 + (size_t)e * FDIM + col);
#pragma unroll
        for (int i = 0; i < 2; i++) {
#pragma unroll
            for (int h = 0; h < 2; h++) {
                int rl = mb + 16 * i + r + 8 * h;
                int rr = m0 + rl;
                if (rr < cnt) {
                    float v0 = siluf(acc1[i][j][2*h+0] + bv1.x) * (acc3[i][j][2*h+0] + bv3.x);
                    float v1 = siluf(acc1[i][j][2*h+1] + bv1.y) * (acc3[i][j][2*h+1] + bv3.y);
                    __half2 hv = __floats2half2_rn(v0, v1);
                    *(__half2*)(g_act + ((size_t)e * NTOK + rr) * FDIM + col) = hv;
                }
            }
        }
    }
}

// ---------------- GEMM2, 256 threads, fused weight convert -------------------
// A (act fp16) via cp.async; B from fp32 W2 [F][H] via LDG+convert+STS+trans.
__global__ __launch_bounds__(256, 2)
void gemm2_kernel(const float* __restrict__ W2, const float* __restrict__ b2,
                  float* __restrict__ out) {
    int e   = blockIdx.z;
    int cnt = g_cnt[e];
    int m0  = blockIdx.x * BM;
    if (m0 >= cnt) return;
    int n0  = blockIdx.y * BN;

    extern __shared__ __align__(16) __half smem[];
    const int STG = ATILE + BTILE;
    __shared__ int   toks[BM];
    __shared__ float ws[BM];

    int tid = threadIdx.x;
    if (tid < BM) {
        int rr = m0 + tid;
        toks[tid] = (rr < cnt) ? g_list[e * NTOK + rr] : -1;
        ws[tid]   = (rr < cnt) ? g_lw  [e * NTOK + rr] : 0.0f;
    }
    __syncthreads();

    // A: 1024 chunks / 256 threads = 4 cp.async
    int arow = tid >> 1, apart = (tid & 1) * 4;
    int ra = (m0 + arow < cnt) ? arow : 0;
    const __half* pA = g_act + ((size_t)e * NTOK + m0 + ra) * FDIM + apart * 8;

    unsigned uS0 = (unsigned)__cvta_generic_to_shared(smem);
    unsigned uA = uS0 + (unsigned)(arow * AS_STR + apart * 8) * 2;

    // B: tile [64 kF][64 nH]; thread handles rows bkrow and bkrow+32, 8 f32 each
    int bkrow = tid >> 3;            // 0..31
    int bnoff = (tid & 7) * 8;       // 0..56
    const float* pW2 = W2 + (size_t)e * FDIM * HDIM + (size_t)bkrow * HDIM + n0 + bnoff;
    int bsts0 = bkrow * AS_STR + bnoff;
    int bsts1 = (bkrow + 32) * AS_STR + bnoff;

    float4 rba, rbb, rbc, rbd;

#define G2_LDGB(kof)                                                             \
    do {                                                                         \
        const float* bp_ = pW2 + (size_t)(kof) * HDIM;                           \
        rba = *(const float4*)(bp_);                                             \
        rbb = *(const float4*)(bp_ + 4);                                         \
        const float* bq_ = bp_ + (size_t)32 * HDIM;                              \
        rbc = *(const float4*)(bq_);                                             \
        rbd = *(const float4*)(bq_ + 4);                                         \
    } while (0)

#define G2_STSB(s)                                                               \
    do {                                                                         \
        uint4 u_;                                                                \
        u_.x = pack2h(rba.x, rba.y); u_.y = pack2h(rba.z, rba.w);                \
        u_.z = pack2h(rbb.x, rbb.y); u_.w = pack2h(rbb.z, rbb.w);                \
        *(uint4*)(smem + (s) * STG + ATILE + bsts0) = u_;                        \
        u_.x = pack2h(rbc.x, rbc.y); u_.y = pack2h(rbc.z, rbc.w);                \
        u_.z = pack2h(rbd.x, rbd.y); u_.w = pack2h(rbd.z, rbd.w);                \
        *(uint4*)(smem + (s) * STG + ATILE + bsts1) = u_;                        \
    } while (0)

#define G2_ISSUEA(s, kof)                                                        \
    do {                                                                         \
        unsigned sb_ = (unsigned)(s) * STG * 2;                                  \
        cpa16(uA + sb_,      pA + (kof));                                        \
        cpa16(uA + sb_ + 16, pA + (kof) + 8);                                    \
        cpa16(uA + sb_ + 32, pA + (kof) + 16);                                   \
        cpa16(uA + sb_ + 48, pA + (kof) + 24);                                   \
        CP_COMMIT();                                                             \
    } while (0)

    G2_LDGB(0);
    G2_STSB(0);
    G2_LDGB(BK);
    G2_ISSUEA(0, 0);
    G2_ISSUEA(1, BK);

    int lane = tid & 31, warp = tid >> 5;
    int wm = warp & 3, wn = warp >> 2;
    int mb = wm * 32, nb = wn * 32;
    int r = lane >> 2, q = lane & 3;

    int lr = lane & 7, lg = lane >> 3;
    int a_row  = mb + lr + 8 * (lg & 1);
    int a_koff = 8 * (lg >> 1);
    unsigned aoff0 = (unsigned)(a_row * AS_STR + a_koff) * 2;
    unsigned aoff1 = aoff0 + (unsigned)(16 * AS_STR) * 2;
    unsigned bT0 = (unsigned)((8 * (lg & 1) + lr) * AS_STR + nb + 8 * (lg >> 1)) * 2;
    unsigned bT1 = bT0 + 16u * 2u;   // +16 n cols
    const unsigned uBrel = (unsigned)ATILE * 2;

    float acc[2][4][4];
#pragma unroll
    for (int i = 0; i < 2; i++)
#pragma unroll
        for (int j = 0; j < 4; j++)
#pragma unroll
            for (int c = 0; c < 4; c++) acc[i][j][c] = 0.f;

    const int NIT = FDIM / BK;   // 64
    for (int it = 0; it < NIT; it++) {
        if (it < NIT - 1) CP_WAIT1(); else CP_WAIT0();
        __syncthreads();
        if (it + 1 < NIT) G2_STSB((it + 1) % NSTG);
        if (it + 2 < NIT) {
            G2_LDGB((it + 2) * BK);
            G2_ISSUEA((it + 2) % NSTG, (it + 2) * BK);
        }

        int st = it % NSTG;
        unsigned uStage = uS0 + (unsigned)(st * STG) * 2;

#pragma unroll
        for (int ks = 0; ks < 4; ks++) {
            unsigned kbA = (unsigned)ks * 32u;
            unsigned kbB = (unsigned)ks * (16u * AS_STR * 2u);
            unsigned af0[4], af1[4];
            LDSM4(af0[0], af0[1], af0[2], af0[3], uStage + aoff0 + kbA);
            LDSM4(af1[0], af1[1], af1[2], af1[3], uStage + aoff1 + kbA);
#pragma unroll
            for (int jj = 0; jj < 2; jj++) {
                unsigned bo = (jj == 0) ? bT0 : bT1;
                unsigned p0, p1, p2, p3;
                LDSM4T(p0, p1, p2, p3, uStage + uBrel + bo + kbB);
                MMA_F16(acc[0][2*jj],   af0[0], af0[1], af0[2], af0[3], p0, p1);
                MMA_F16(acc[1][2*jj],   af1[0], af1[1], af1[2], af1[3], p0, p1);
                MMA_F16(acc[0][2*jj+1], af0[0], af0[1], af0[2], af0[3], p2, p3);
                MMA_F16(acc[1][2*jj+1], af1[0], af1[1], af1[2], af1[3], p2, p3);
            }
        }
    }
#undef G2_LDGB
#undef G2_STSB
#undef G2_ISSUEA

#pragma unroll
    for (int j = 0; j < 4; j++) {
        int col = n0 + nb + 8 * j + q * 2;
        float2 bv = *(const float2*)(b2 + (size_t)e * HDIM + col);
#pragma unroll
        for (int i = 0; i < 2; i++) {
#pragma unroll
            for (int h = 0; h < 2; h++) {
                int rl = mb + 16 * i + r + 8 * h;
                int rr = m0 + rl;
                if (rr < cnt) {
                    int tok = toks[rl];
                    float w = ws[rl];
                    float* op = out + (size_t)tok * HDIM + col;
                    atomicAdd(op + 0, w * (acc[i][j][2*h+0] + bv.x));
                    atomicAdd(op + 1, w * (acc[i][j][2*h+1] + bv.y));
                }
            }
        }
    }
}

// ---------------- launch -----------------------------------------------------
extern "C" void kernel_launch(void* const* d_in, const int* in_sizes, int n_in,
                              void* d_out, int out_size) {
    const float* x     = (const float*)d_in[0];
    const float* noise = (const float*)d_in[1];
    const float* Wg    = (const float*)d_in[2];
    const float* bg    = (const float*)d_in[3];
    const float* W1    = (const float*)d_in[4];
    const float* b1    = (const float*)d_in[5];
    const float* W2    = (const float*)d_in[6];
    const float* b2    = (const float*)d_in[7];
    const float* W3    = (const float*)d_in[8];
    const float* b3    = (const float*)d_in[9];

    float* out = (float*)d_out;
    const size_t HID = (size_t)NTOK * HDIM;
    const size_t LOG = (size_t)NTOK * NEXP;
    const size_t SEL = (size_t)NTOK * TOPK;

    float* out_logits = nullptr;
    float* out_sel    = nullptr;
    if ((size_t)out_size >= HID + LOG)       out_logits = out + HID;
    if ((size_t)out_size >= HID + LOG + SEL) out_sel    = out + HID + LOG;

    convert_x_kernel<<<(NTOK * HDIM / 4) / 256, 256>>>(x);
    router_kernel<<<NTOK, 128>>>(x, noise, Wg, bg, out_logits, out_sel);
    build_lists_kernel<<<1, 1024>>>();
    cudaMemsetAsync(out, 0, HID * sizeof(float));

    const int smem1 = NSTG * (ATILE + 2 * BTILE) * sizeof(__half);  // 110592
    const int smem2 = NSTG * (ATILE + BTILE) * sizeof(__half);      // 82944
    cudaFuncSetAttribute(gemm1_kernel, cudaFuncAttributeMaxDynamicSharedMemorySize, smem1);
    cudaFuncSetAttribute(gemm2_kernel, cudaFuncAttributeMaxDynamicSharedMemorySize, smem2);

    dim3 g1(NTOK / BM, FDIM / BN, NEXP);   // (16, 64, 8), M fastest
    gemm1_kernel<<<g1, 512, smem1>>>(W1, b1, W3, b3);

    dim3 g2(NTOK / BM, HDIM / BN, NEXP);   // (16, 16, 8)
    gemm2_kernel<<<g2, 256, smem2>>>(W2, b2, out);
}